// round 4
// baseline (speedup 1.0000x reference)
#include <cuda_runtime.h>
#include <cuda_bf16.h>
#include <cstdint>
#include <cstddef>

typedef unsigned int u32;

#define BN 4
#define TT 2048
#define CC 1024
#define MROWS (BN*TT)   // 8192

// ======================= device scratch (no allocs allowed) =======================
__device__ __align__(256) __nv_bfloat16 g_xh[MROWS*CC];
__device__ __align__(256) __nv_bfloat16 g_xl[MROWS*CC];
__device__ __align__(256) __nv_bfloat16 g_wh[4*CC*CC];
__device__ __align__(256) __nv_bfloat16 g_wl[4*CC*CC];
__device__ __align__(256) __nv_bfloat16 g_qh[MROWS*CC];
__device__ __align__(256) __nv_bfloat16 g_ql[MROWS*CC];
__device__ __align__(256) __nv_bfloat16 g_kh[MROWS*CC];
__device__ __align__(256) __nv_bfloat16 g_kl[MROWS*CC];
__device__ __align__(256) __nv_bfloat16 g_vth[MROWS*CC];  // V^T: [b][d][s]
__device__ __align__(256) __nv_bfloat16 g_vtl[MROWS*CC];
__device__ __align__(256) float         g_s [(size_t)BN*TT*TT];
__device__ __align__(256) __nv_bfloat16 g_ph[(size_t)BN*TT*TT];
__device__ __align__(256) __nv_bfloat16 g_pl[(size_t)BN*TT*TT];
__device__ __align__(256) __nv_bfloat16 g_ch[MROWS*CC];
__device__ __align__(256) __nv_bfloat16 g_cl[MROWS*CC];

// ======================= PTX helpers (sm_100 baseline, NO 'a' features) =======================
__device__ __forceinline__ u32 smem_u32(const void* p) {
    u32 a;
    asm("{ .reg .u64 t; cvta.to.shared.u64 t, %1; cvt.u32.u64 %0, t; }" : "=r"(a) : "l"(p));
    return a;
}
__device__ __forceinline__ void cpa16(u32 dst, const void* src) {
    asm volatile("cp.async.cg.shared.global [%0], [%1], 16;" :: "r"(dst), "l"(src) : "memory");
}
#define CP_COMMIT() asm volatile("cp.async.commit_group;" ::: "memory")
#define CP_WAIT(n)  asm volatile("cp.async.wait_group %0;" :: "n"(n) : "memory")

#define LDSM4(d0,d1,d2,d3,a) \
    asm volatile("ldmatrix.sync.aligned.m8n8.x4.shared.b16 {%0,%1,%2,%3}, [%4];" \
                 : "=r"(d0),"=r"(d1),"=r"(d2),"=r"(d3) : "r"(a))
#define LDSM2(d0,d1,a) \
    asm volatile("ldmatrix.sync.aligned.m8n8.x2.shared.b16 {%0,%1}, [%2];" \
                 : "=r"(d0),"=r"(d1) : "r"(a))

__device__ __forceinline__ void mma16816(float* c, const u32* a, const u32* b) {
    asm volatile(
        "mma.sync.aligned.m16n8k16.row.col.f32.bf16.bf16.f32 "
        "{%0,%1,%2,%3}, {%4,%5,%6,%7}, {%8,%9}, {%0,%1,%2,%3};"
        : "+f"(c[0]), "+f"(c[1]), "+f"(c[2]), "+f"(c[3])
        : "r"(a[0]), "r"(a[1]), "r"(a[2]), "r"(a[3]), "r"(b[0]), "r"(b[1]));
}

__device__ __forceinline__ u32 pack_bf2(__nv_bfloat16 a, __nv_bfloat16 b) {
    __nv_bfloat162 t = __halves2bfloat162(a, b);
    return *reinterpret_cast<u32*>(&t);
}
__device__ __forceinline__ unsigned short bf_bits(__nv_bfloat16 h) {
    return *reinterpret_cast<unsigned short*>(&h);
}

// ======================= GEMM kernel =======================
// Tile 128 x NT, K-chunk 64. Stage: Ah(16K) Al(16K) Bh(NT*128) Bl(NT*128).
// NT=256: 96KB/stage x2 = 192KB. NT=128: 64KB/stage x2 = 128KB.

// MODE 0: split bf16 hi/lo row-major (+optional bias, +batch stride on C)
// MODE 1: V-projection: bias then transposed split store into vt[b][d][s] (NT=128 only)
// MODE 2: fp32 * scale row-major (+batch stride on C)
// MODE 3: fp32 + bias row-major (final output)
template<int MODE, int NT>
__global__ void __launch_bounds__(256, 1) gemm_bf16x3(
    const __nv_bfloat16* __restrict__ Ah, const __nv_bfloat16* __restrict__ Al,
    const __nv_bfloat16* __restrict__ Bh, const __nv_bfloat16* __restrict__ Bl,
    int lda, int ldb, int K,
    long long sAz, long long sBz, long long sCz,
    const float* __restrict__ bias, float scale,
    __nv_bfloat16* __restrict__ outH, __nv_bfloat16* __restrict__ outL,
    float* __restrict__ outF, int ldc)
{
    constexpr int BCNT = NT / 32;               // B 8-row tiles per warp
    constexpr u32 ST   = 32768u + 2u * (u32)NT * 128u;
    constexpr int BCH  = (NT == 256) ? 8 : 4;   // B cp.async 16B chunks per thread

    extern __shared__ __align__(1024) char smem_raw[];
    const u32 sb0 = smem_u32(smem_raw);
    const u32 sb  = (sb0 + 1023u) & ~1023u;
    char* smem_ptr = smem_raw + (sb - sb0);

    const int tid  = threadIdx.x;
    const int lane = tid & 31, wid = tid >> 5;
    const int wm = wid & 1, wn = wid >> 1;          // 2 x 4 warp grid
    const int m0 = blockIdx.x * 128, n0 = blockIdx.y * NT;
    const long long z = blockIdx.z;
    Ah += z * sAz; Al += z * sAz; Bh += z * sBz; Bl += z * sBz;

    float acc[4][BCNT][4];
    #pragma unroll
    for (int i = 0; i < 4; ++i)
        #pragma unroll
        for (int j = 0; j < BCNT; ++j)
            #pragma unroll
            for (int e = 0; e < 4; ++e) acc[i][j][e] = 0.f;

    // ---- cp.async loader ----
    const int rA_ld = tid >> 1;
    const int cA_ld = (tid & 1) * 4;
    const __nv_bfloat16* gAh = Ah + (size_t)(m0 + rA_ld) * lda + cA_ld * 8;
    const __nv_bfloat16* gAl = Al + (size_t)(m0 + rA_ld) * lda + cA_ld * 8;
    const int rB_ld = (NT == 256) ? tid : (tid >> 1);
    const int cB_ld = (NT == 256) ? 0 : (tid & 1) * 4;
    const __nv_bfloat16* gBh = Bh + (size_t)(n0 + rB_ld) * ldb + cB_ld * 8;
    const __nv_bfloat16* gBl = Bl + (size_t)(n0 + rB_ld) * ldb + cB_ld * 8;

    u32 swA[4], swB[BCH];
    #pragma unroll
    for (int j = 0; j < 4; ++j) {
        u32 c16 = (u32)(cA_ld + j);
        swA[j] = (u32)rA_ld * 128u + ((c16 ^ ((u32)rA_ld & 7u)) << 4);
    }
    #pragma unroll
    for (int j = 0; j < BCH; ++j) {
        u32 c16 = (u32)(cB_ld + j);
        swB[j] = (u32)rB_ld * 128u + ((c16 ^ ((u32)rB_ld & 7u)) << 4);
    }

    auto load_stage = [&](int s, int k0) {
        const u32 b = sb + (u32)s * ST;
        #pragma unroll
        for (int j = 0; j < 4; ++j) {
            cpa16(b + swA[j],           gAh + k0 + j * 8);
            cpa16(b + 16384u + swA[j],  gAl + k0 + j * 8);
        }
        #pragma unroll
        for (int j = 0; j < BCH; ++j) {
            cpa16(b + 32768u + swB[j],                  gBh + k0 + j * 8);
            cpa16(b + 32768u + (u32)NT*128u + swB[j],   gBl + k0 + j * 8);
        }
        CP_COMMIT();
    };

    const int nch = K >> 6;
    load_stage(0, 0);
    if (nch > 1) load_stage(1, 64);

    const int rAf = lane & 15, cAf = lane >> 4;        // ldmatrix x4 lane map (A)
    const int rBf = lane & 7,  cBf = (lane >> 3) & 1;  // ldmatrix x2 lane map (B)

    for (int c = 0; c < nch; ++c) {
        if (c + 1 < nch) { CP_WAIT(1); } else { CP_WAIT(0); }
        __syncthreads();
        const u32 base = sb + (u32)(c & 1) * ST;

        #pragma unroll
        for (int ks = 0; ks < 4; ++ks) {
            // --- load A-hi + B-hi, combo 1 ---
            u32 ah[4][4];
            #pragma unroll
            for (int am = 0; am < 4; ++am) {
                const int row = wm * 64 + am * 16 + rAf;
                const u32 a = base + (u32)row * 128u
                            + ((u32)((ks * 2 + cAf) ^ (row & 7)) << 4);
                LDSM4(ah[am][0], ah[am][1], ah[am][2], ah[am][3], a);
            }
            u32 bb[BCNT][2];
            u32 baddr[BCNT];
            #pragma unroll
            for (int bn = 0; bn < BCNT; ++bn) {
                const int row = wn * (NT / 4) + bn * 8 + rBf;
                baddr[bn] = base + 32768u + (u32)row * 128u
                          + ((u32)((ks * 2 + cBf) ^ (row & 7)) << 4);
                LDSM2(bb[bn][0], bb[bn][1], baddr[bn]);
            }
            #pragma unroll
            for (int am = 0; am < 4; ++am)
                #pragma unroll
                for (int bn = 0; bn < BCNT; ++bn)
                    mma16816(acc[am][bn], ah[am], bb[bn]);

            // --- load A-lo, combo 2 (Al x Bh) ---
            u32 a2[4][4];
            #pragma unroll
            for (int am = 0; am < 4; ++am) {
                const int row = wm * 64 + am * 16 + rAf;
                const u32 a = base + 16384u + (u32)row * 128u
                            + ((u32)((ks * 2 + cAf) ^ (row & 7)) << 4);
                LDSM4(a2[am][0], a2[am][1], a2[am][2], a2[am][3], a);
            }
            #pragma unroll
            for (int am = 0; am < 4; ++am)
                #pragma unroll
                for (int bn = 0; bn < BCNT; ++bn)
                    mma16816(acc[am][bn], a2[am], bb[bn]);

            // --- reload B with lo, combo 3 (Ah x Bl) ---
            #pragma unroll
            for (int bn = 0; bn < BCNT; ++bn)
                LDSM2(bb[bn][0], bb[bn][1], baddr[bn] + (u32)NT * 128u);
            #pragma unroll
            for (int am = 0; am < 4; ++am)
                #pragma unroll
                for (int bn = 0; bn < BCNT; ++bn)
                    mma16816(acc[am][bn], ah[am], bb[bn]);
        }
        __syncthreads();
        if (c + 2 < nch) load_stage(c & 1, (c + 2) * 64);
    }

    // ======================= epilogue =======================
    const int q = lane >> 2, tq = lane & 3;

    if constexpr (MODE == 1) {
        // transpose 128x128 tile through smem (u32 = packed hi|lo), stride 132
        u32* T = reinterpret_cast<u32*>(smem_ptr);
        #pragma unroll
        for (int am = 0; am < 4; ++am)
            #pragma unroll
            for (int bn = 0; bn < BCNT; ++bn)
                #pragma unroll
                for (int e = 0; e < 4; ++e) {
                    const int ml = wm * 64 + am * 16 + q + (e >> 1) * 8;
                    const int nl = wn * (NT / 4) + bn * 8 + 2 * tq + (e & 1);
                    const float v = acc[am][bn][e] + bias[n0 + nl];
                    const __nv_bfloat16 h = __float2bfloat16(v);
                    const __nv_bfloat16 l = __float2bfloat16(v - __bfloat162float(h));
                    T[nl * 132 + ml] = ((u32)bf_bits(l) << 16) | (u32)bf_bits(h);
                }
        __syncthreads();
        const int d  = tid >> 1;
        const int mh = (tid & 1) * 64;
        const int b  = m0 >> 11;
        const size_t idx = ((size_t)b * CC + (n0 + d)) * TT + (m0 & 2047) + mh;
        #pragma unroll
        for (int i = 0; i < 64; i += 8) {
            u32 hw[4], lw[4];
            #pragma unroll
            for (int p = 0; p < 4; ++p) {
                const u32 t0 = T[d * 132 + mh + i + 2 * p];
                const u32 t1 = T[d * 132 + mh + i + 2 * p + 1];
                hw[p] = (t0 & 0xffffu) | (t1 << 16);
                lw[p] = (t0 >> 16)     | (t1 & 0xffff0000u);
            }
            *reinterpret_cast<uint4*>(outH + idx + i) = make_uint4(hw[0], hw[1], hw[2], hw[3]);
            *reinterpret_cast<uint4*>(outL + idx + i) = make_uint4(lw[0], lw[1], lw[2], lw[3]);
        }
        return;
    } else {

    if (MODE == 0) { outH += z * sCz; outL += z * sCz; }
    else           { outF += z * sCz; }

    #pragma unroll
    for (int am = 0; am < 4; ++am)
        #pragma unroll
        for (int e2 = 0; e2 < 2; ++e2) {
            const int gm = m0 + wm * 64 + am * 16 + q + e2 * 8;
            #pragma unroll
            for (int bn = 0; bn < BCNT; ++bn) {
                const int gn = n0 + wn * (NT / 4) + bn * 8 + 2 * tq;
                float v0 = acc[am][bn][e2 * 2 + 0];
                float v1 = acc[am][bn][e2 * 2 + 1];
                if (MODE == 0) {
                    if (bias) { v0 += bias[gn]; v1 += bias[gn + 1]; }
                    const __nv_bfloat16 h0 = __float2bfloat16(v0), h1 = __float2bfloat16(v1);
                    const __nv_bfloat16 l0 = __float2bfloat16(v0 - __bfloat162float(h0));
                    const __nv_bfloat16 l1 = __float2bfloat16(v1 - __bfloat162float(h1));
                    *reinterpret_cast<u32*>(outH + (size_t)gm * ldc + gn) = pack_bf2(h0, h1);
                    *reinterpret_cast<u32*>(outL + (size_t)gm * ldc + gn) = pack_bf2(l0, l1);
                } else if (MODE == 2) {
                    float2 val; val.x = v0 * scale; val.y = v1 * scale;
                    *reinterpret_cast<float2*>(outF + (size_t)gm * ldc + gn) = val;
                } else {
                    float2 val; val.x = v0 + bias[gn]; val.y = v1 + bias[gn + 1];
                    *reinterpret_cast<float2*>(outF + (size_t)gm * ldc + gn) = val;
                }
            }
        }
    }
}

// ======================= split fp32 -> bf16 hi/lo =======================
__global__ void __launch_bounds__(256) split_kernel(
    const float* __restrict__ x, __nv_bfloat16* __restrict__ h,
    __nv_bfloat16* __restrict__ l, int n4)
{
    int i = blockIdx.x * 256 + threadIdx.x;
    if (i >= n4) return;
    float4 v = reinterpret_cast<const float4*>(x)[i];
    float vv[4] = { v.x, v.y, v.z, v.w };
    __nv_bfloat16 hh[4], ll[4];
    #pragma unroll
    for (int c = 0; c < 4; ++c) {
        hh[c] = __float2bfloat16(vv[c]);
        ll[c] = __float2bfloat16(vv[c] - __bfloat162float(hh[c]));
    }
    *reinterpret_cast<uint2*>(h + 4*(size_t)i) = make_uint2(pack_bf2(hh[0],hh[1]), pack_bf2(hh[2],hh[3]));
    *reinterpret_cast<uint2*>(l + 4*(size_t)i) = make_uint2(pack_bf2(ll[0],ll[1]), pack_bf2(ll[2],ll[3]));
}

// ======================= softmax + split =======================
__global__ void __launch_bounds__(256) softmax_split_kernel(
    const float* __restrict__ S, __nv_bfloat16* __restrict__ Ph, __nv_bfloat16* __restrict__ Pl)
{
    __shared__ float red[8];
    __shared__ float sM, sInv;
    const size_t row = blockIdx.x;
    const float4* src = reinterpret_cast<const float4*>(S + row * TT);
    const int t = threadIdx.x, w = t >> 5, ln = t & 31;

    float4 a = src[t], b2 = src[t + 256];
    float mx = fmaxf(fmaxf(fmaxf(a.x, a.y), fmaxf(a.z, a.w)),
                     fmaxf(fmaxf(b2.x, b2.y), fmaxf(b2.z, b2.w)));
    #pragma unroll
    for (int o = 16; o; o >>= 1) mx = fmaxf(mx, __shfl_xor_sync(0xffffffffu, mx, o));
    if (ln == 0) red[w] = mx;
    __syncthreads();
    if (t == 0) {
        float m = red[0];
        #pragma unroll
        for (int i = 1; i < 8; ++i) m = fmaxf(m, red[i]);
        sM = m;
    }
    __syncthreads();
    const float M = sM;

    float e[8];
    e[0] = __expf(a.x - M);  e[1] = __expf(a.y - M);
    e[2] = __expf(a.z - M);  e[3] = __expf(a.w - M);
    e[4] = __expf(b2.x - M); e[5] = __expf(b2.y - M);
    e[6] = __expf(b2.z - M); e[7] = __expf(b2.w - M);
    float sm = e[0]+e[1]+e[2]+e[3]+e[4]+e[5]+e[6]+e[7];
    #pragma unroll
    for (int o = 16; o; o >>= 1) sm += __shfl_xor_sync(0xffffffffu, sm, o);
    __syncthreads();
    if (ln == 0) red[w] = sm;
    __syncthreads();
    if (t == 0) {
        float ssum = 0.f;
        #pragma unroll
        for (int i = 0; i < 8; ++i) ssum += red[i];
        sInv = 1.0f / ssum;
    }
    __syncthreads();
    const float inv = sInv;

    #pragma unroll
    for (int half = 0; half < 2; ++half) {
        __nv_bfloat16 hh[4], ll[4];
        #pragma unroll
        for (int c = 0; c < 4; ++c) {
            float p = e[half*4 + c] * inv;
            hh[c] = __float2bfloat16(p);
            ll[c] = __float2bfloat16(p - __bfloat162float(hh[c]));
        }
        size_t off = row * TT + (size_t)(t + half*256) * 4;
        *reinterpret_cast<uint2*>(Ph + off) = make_uint2(pack_bf2(hh[0],hh[1]), pack_bf2(hh[2],hh[3]));
        *reinterpret_cast<uint2*>(Pl + off) = make_uint2(pack_bf2(ll[0],ll[1]), pack_bf2(ll[2],ll[3]));
    }
}

// ======================= host launch =======================
static void* sym_addr(const void* s) {
    void* p = nullptr;
    cudaGetSymbolAddress(&p, s);
    return p;
}

#define SMEM_256 (1024 + 2*(32768 + 2*256*128))   // 197632
#define SMEM_128 (1024 + 2*(32768 + 2*128*128))   // 132096

extern "C" void kernel_launch(void* const* d_in, const int* in_sizes, int n_in,
                              void* d_out, int out_size) {
    (void)in_sizes; (void)n_in; (void)out_size;
    const float* x  = (const float*)d_in[0];
    const float* Wq = (const float*)d_in[1];
    const float* bq = (const float*)d_in[2];
    const float* Wk = (const float*)d_in[3];
    const float* bk = (const float*)d_in[4];
    const float* Wv = (const float*)d_in[5];
    const float* bv = (const float*)d_in[6];
    const float* Wo = (const float*)d_in[7];
    const float* bo = (const float*)d_in[8];
    float* out = (float*)d_out;

    __nv_bfloat16* xh  = (__nv_bfloat16*)sym_addr(g_xh);
    __nv_bfloat16* xl  = (__nv_bfloat16*)sym_addr(g_xl);
    __nv_bfloat16* wh  = (__nv_bfloat16*)sym_addr(g_wh);
    __nv_bfloat16* wl  = (__nv_bfloat16*)sym_addr(g_wl);
    __nv_bfloat16* qh  = (__nv_bfloat16*)sym_addr(g_qh);
    __nv_bfloat16* ql  = (__nv_bfloat16*)sym_addr(g_ql);
    __nv_bfloat16* kh  = (__nv_bfloat16*)sym_addr(g_kh);
    __nv_bfloat16* kl  = (__nv_bfloat16*)sym_addr(g_kl);
    __nv_bfloat16* vth = (__nv_bfloat16*)sym_addr(g_vth);
    __nv_bfloat16* vtl = (__nv_bfloat16*)sym_addr(g_vtl);
    float*         sS  = (float*)sym_addr(g_s);
    __nv_bfloat16* ph  = (__nv_bfloat16*)sym_addr(g_ph);
    __nv_bfloat16* pl  = (__nv_bfloat16*)sym_addr(g_pl);
    __nv_bfloat16* ch  = (__nv_bfloat16*)sym_addr(g_ch);
    __nv_bfloat16* cl  = (__nv_bfloat16*)sym_addr(g_cl);

    cudaFuncSetAttribute(gemm_bf16x3<0,256>, cudaFuncAttributeMaxDynamicSharedMemorySize, SMEM_256);
    cudaFuncSetAttribute(gemm_bf16x3<2,256>, cudaFuncAttributeMaxDynamicSharedMemorySize, SMEM_256);
    cudaFuncSetAttribute(gemm_bf16x3<3,256>, cudaFuncAttributeMaxDynamicSharedMemorySize, SMEM_256);
    cudaFuncSetAttribute(gemm_bf16x3<1,128>, cudaFuncAttributeMaxDynamicSharedMemorySize, SMEM_128);

    // splits
    split_kernel<<<(MROWS*CC/4 + 255)/256, 256>>>(x,  xh, xl, MROWS*CC/4);
    split_kernel<<<(CC*CC/4 + 255)/256, 256>>>(Wq, wh + 0*(size_t)CC*CC, wl + 0*(size_t)CC*CC, CC*CC/4);
    split_kernel<<<(CC*CC/4 + 255)/256, 256>>>(Wk, wh + 1*(size_t)CC*CC, wl + 1*(size_t)CC*CC, CC*CC/4);
    split_kernel<<<(CC*CC/4 + 255)/256, 256>>>(Wv, wh + 2*(size_t)CC*CC, wl + 2*(size_t)CC*CC, CC*CC/4);
    split_kernel<<<(CC*CC/4 + 255)/256, 256>>>(Wo, wh + 3*(size_t)CC*CC, wl + 3*(size_t)CC*CC, CC*CC/4);

    // Q = x Wq^T + bq
    dim3 gProj(MROWS/128, CC/256, 1);     // (64, 4)
    gemm_bf16x3<0,256><<<gProj, 256, SMEM_256>>>(xh, xl, wh + 0*(size_t)CC*CC, wl + 0*(size_t)CC*CC,
        CC, CC, CC, 0, 0, 0, bq, 1.f, qh, ql, nullptr, CC);
    // K
    gemm_bf16x3<0,256><<<gProj, 256, SMEM_256>>>(xh, xl, wh + 1*(size_t)CC*CC, wl + 1*(size_t)CC*CC,
        CC, CC, CC, 0, 0, 0, bk, 1.f, kh, kl, nullptr, CC);
    // V -> transposed store vt[b][d][s] (128-wide tile)
    dim3 gV(MROWS/128, CC/128, 1);        // (64, 8)
    gemm_bf16x3<1,128><<<gV, 256, SMEM_128>>>(xh, xl, wh + 2*(size_t)CC*CC, wl + 2*(size_t)CC*CC,
        CC, CC, CC, 0, 0, 0, bv, 1.f, vth, vtl, nullptr, 0);

    // scores = Q K^T / 32  (per batch)
    dim3 gScore(TT/128, TT/256, BN);      // (16, 8, 4)
    gemm_bf16x3<2,256><<<gScore, 256, SMEM_256>>>(qh, ql, kh, kl,
        CC, CC, CC, (long long)TT*CC, (long long)TT*CC, (long long)TT*TT,
        nullptr, 0.03125f, nullptr, nullptr, sS, TT);

    // softmax + split
    softmax_split_kernel<<<MROWS, 256>>>(sS, ph, pl);

    // ctx = P V  (A = P [t][s], B = vt [d][s], per batch)
    dim3 gPV(TT/128, CC/256, BN);         // (16, 4, 4)
    gemm_bf16x3<0,256><<<gPV, 256, SMEM_256>>>(ph, pl, vth, vtl,
        TT, TT, TT, (long long)TT*TT, (long long)CC*TT, (long long)TT*CC,
        nullptr, 1.f, ch, cl, nullptr, CC);

    // out = ctx Wo^T + bo  (fp32 -> d_out)
    dim3 gOut(MROWS/128, CC/256, 1);      // (64, 4)
    gemm_bf16x3<3,256><<<gOut, 256, SMEM_256>>>(ch, cl, wh + 3*(size_t)CC*CC, wl + 3*(size_t)CC*CC,
        CC, CC, CC, 0, 0, 0, bo, 1.f, nullptr, nullptr, out, CC);
}

// round 5
// speedup vs baseline: 1.1230x; 1.1230x over previous
#include <cuda_runtime.h>
#include <cuda_bf16.h>
#include <cstdint>
#include <cstddef>

typedef unsigned int u32;

#define BN 4
#define TT 2048
#define CC 1024
#define MROWS (BN*TT)   // 8192

// ======================= device scratch (no allocs allowed) =======================
__device__ __align__(256) __nv_bfloat16 g_xh[MROWS*CC];
__device__ __align__(256) __nv_bfloat16 g_xl[MROWS*CC];
__device__ __align__(256) __nv_bfloat16 g_wh[4*CC*CC];
__device__ __align__(256) __nv_bfloat16 g_wl[4*CC*CC];
__device__ __align__(256) __nv_bfloat16 g_qh[MROWS*CC];
__device__ __align__(256) __nv_bfloat16 g_ql[MROWS*CC];
__device__ __align__(256) __nv_bfloat16 g_kh[MROWS*CC];
__device__ __align__(256) __nv_bfloat16 g_kl[MROWS*CC];
__device__ __align__(256) __nv_bfloat16 g_vth[MROWS*CC];  // V^T: [b][d][s]
__device__ __align__(256) __nv_bfloat16 g_vtl[MROWS*CC];
__device__ __align__(256) float         g_s [(size_t)BN*TT*TT];
__device__ __align__(256) __nv_bfloat16 g_ph[(size_t)BN*TT*TT];
__device__ __align__(256) __nv_bfloat16 g_pl[(size_t)BN*TT*TT];
__device__ __align__(256) __nv_bfloat16 g_ch[MROWS*CC];
__device__ __align__(256) __nv_bfloat16 g_cl[MROWS*CC];

// ======================= PTX helpers (sm_100 baseline, NO 'a' features) =======================
__device__ __forceinline__ u32 smem_u32(const void* p) {
    u32 a;
    asm("{ .reg .u64 t; cvta.to.shared.u64 t, %1; cvt.u32.u64 %0, t; }" : "=r"(a) : "l"(p));
    return a;
}
__device__ __forceinline__ void cpa16(u32 dst, const void* src) {
    asm volatile("cp.async.cg.shared.global [%0], [%1], 16;" :: "r"(dst), "l"(src) : "memory");
}
#define CP_COMMIT() asm volatile("cp.async.commit_group;" ::: "memory")
#define CP_WAIT(n)  asm volatile("cp.async.wait_group %0;" :: "n"(n) : "memory")

#define LDSM4(d0,d1,d2,d3,a) \
    asm volatile("ldmatrix.sync.aligned.m8n8.x4.shared.b16 {%0,%1,%2,%3}, [%4];" \
                 : "=r"(d0),"=r"(d1),"=r"(d2),"=r"(d3) : "r"(a))
#define LDSM2(d0,d1,a) \
    asm volatile("ldmatrix.sync.aligned.m8n8.x2.shared.b16 {%0,%1}, [%2];" \
                 : "=r"(d0),"=r"(d1) : "r"(a))

__device__ __forceinline__ void mma16816(float* c, const u32* a, const u32* b) {
    asm volatile(
        "mma.sync.aligned.m16n8k16.row.col.f32.bf16.bf16.f32 "
        "{%0,%1,%2,%3}, {%4,%5,%6,%7}, {%8,%9}, {%0,%1,%2,%3};"
        : "+f"(c[0]), "+f"(c[1]), "+f"(c[2]), "+f"(c[3])
        : "r"(a[0]), "r"(a[1]), "r"(a[2]), "r"(a[3]), "r"(b[0]), "r"(b[1]));
}

__device__ __forceinline__ u32 pack_bf2(__nv_bfloat16 a, __nv_bfloat16 b) {
    __nv_bfloat162 t = __halves2bfloat162(a, b);
    return *reinterpret_cast<u32*>(&t);
}
__device__ __forceinline__ unsigned short bf_bits(__nv_bfloat16 h) {
    return *reinterpret_cast<unsigned short*>(&h);
}

// ======================= GEMM kernel =======================
// Tile 128x128, K-chunk 64. Stage: Ah(16K) Al(16K) Bh(16K) Bl(16K) = 64KB; 3 stages.
#define ST_BYTES   65536u
#define NSTAGE     3
#define SMEM_BYTES (1024 + NSTAGE*65536)   // 197632

// MODE 0: split bf16 hi/lo row-major (+optional bias, +batch stride on C)
// MODE 1: V-projection: bias then transposed split store into vt[b][d][s]
// MODE 2: fp32 * scale row-major (+batch stride on C)
// MODE 3: fp32 + bias row-major (final output)
template<int MODE>
__global__ void __launch_bounds__(256, 1) gemm_bf16x3(
    const __nv_bfloat16* __restrict__ Ah, const __nv_bfloat16* __restrict__ Al,
    const __nv_bfloat16* __restrict__ Bh, const __nv_bfloat16* __restrict__ Bl,
    int lda, int ldb, int K,
    long long sAz, long long sBz, long long sCz,
    const float* __restrict__ bias, float scale,
    __nv_bfloat16* __restrict__ outH, __nv_bfloat16* __restrict__ outL,
    float* __restrict__ outF, int ldc)
{
    extern __shared__ __align__(1024) char smem_raw[];
    const u32 sb0 = smem_u32(smem_raw);
    const u32 sb  = (sb0 + 1023u) & ~1023u;
    char* smem_ptr = smem_raw + (sb - sb0);

    const int tid  = threadIdx.x;
    const int lane = tid & 31, wid = tid >> 5;
    const int wm = wid & 1, wn = wid >> 1;          // 2 x 4 warp grid
    const int m0 = blockIdx.x * 128, n0 = blockIdx.y * 128;
    const long long z = blockIdx.z;
    Ah += z * sAz; Al += z * sAz; Bh += z * sBz; Bl += z * sBz;

    float acc[4][4][4];
    #pragma unroll
    for (int i = 0; i < 4; ++i)
        #pragma unroll
        for (int j = 0; j < 4; ++j)
            #pragma unroll
            for (int e = 0; e < 4; ++e) acc[i][j][e] = 0.f;

    // ---- cp.async loader: thread t -> row t/2, 4x16B chunks at (t&1)*4 ----
    const int r  = tid >> 1;
    const int c0 = (tid & 1) * 4;
    const __nv_bfloat16* gAh = Ah + (size_t)(m0 + r) * lda + c0 * 8;
    const __nv_bfloat16* gAl = Al + (size_t)(m0 + r) * lda + c0 * 8;
    const __nv_bfloat16* gBh = Bh + (size_t)(n0 + r) * ldb + c0 * 8;
    const __nv_bfloat16* gBl = Bl + (size_t)(n0 + r) * ldb + c0 * 8;
    u32 swoff[4];
    #pragma unroll
    for (int j = 0; j < 4; ++j) {
        u32 c16 = (u32)(c0 + j);
        swoff[j] = (u32)r * 128u + ((c16 ^ ((u32)r & 7u)) << 4);
    }

    auto load_stage = [&](int s, int k0) {
        const u32 b = sb + (u32)s * ST_BYTES;
        #pragma unroll
        for (int j = 0; j < 4; ++j) {
            const u32 dst = b + swoff[j];
            cpa16(dst,           gAh + k0 + j * 8);
            cpa16(dst + 16384u,  gAl + k0 + j * 8);
            cpa16(dst + 32768u,  gBh + k0 + j * 8);
            cpa16(dst + 49152u,  gBl + k0 + j * 8);
        }
        CP_COMMIT();
    };

    const int nch = K >> 6;
    load_stage(0, 0);
    load_stage(1, 64);   // all our K >= 128, so nch >= 2 always

    const int rA = lane & 15, cA = lane >> 4;          // ldmatrix x4 lane map (A)
    const int rB = lane & 7,  cB = (lane >> 3) & 1;    // ldmatrix x2 lane map (B)

    int sc = 0;          // stage of chunk c
    for (int c = 0; c < nch; ++c) {
        // arrival of chunk c's data (committed 2 groups before the newest)
        if (c + 1 < nch) { CP_WAIT(1); } else { CP_WAIT(0); }
        __syncthreads();   // data visibility + all warps done reading stage being overwritten

        // prefetch chunk c+2 into the stage that chunk c-1 just finished with
        if (c + 2 < nch) {
            int sl = sc + 2; if (sl >= NSTAGE) sl -= NSTAGE;
            load_stage(sl, (c + 2) * 64);
        }

        const u32 base = sb + (u32)sc * ST_BYTES;
        #pragma unroll
        for (int ks = 0; ks < 4; ++ks) {
            // --- A-hi + B-hi, combo 1 ---
            u32 ah[4][4];
            #pragma unroll
            for (int am = 0; am < 4; ++am) {
                const int row = wm * 64 + am * 16 + rA;
                const u32 a = base + (u32)row * 128u
                            + ((u32)((ks * 2 + cA) ^ (row & 7)) << 4);
                LDSM4(ah[am][0], ah[am][1], ah[am][2], ah[am][3], a);
            }
            u32 bb[4][2];
            u32 baddr[4];
            #pragma unroll
            for (int bn = 0; bn < 4; ++bn) {
                const int row = wn * 32 + bn * 8 + rB;
                baddr[bn] = base + 32768u + (u32)row * 128u
                          + ((u32)((ks * 2 + cB) ^ (row & 7)) << 4);
                LDSM2(bb[bn][0], bb[bn][1], baddr[bn]);
            }
            #pragma unroll
            for (int am = 0; am < 4; ++am)
                #pragma unroll
                for (int bn = 0; bn < 4; ++bn)
                    mma16816(acc[am][bn], ah[am], bb[bn]);

            // --- A-lo, combo 2 (Al x Bh, reuse bb) ---
            u32 a2[4][4];
            #pragma unroll
            for (int am = 0; am < 4; ++am) {
                const int row = wm * 64 + am * 16 + rA;
                const u32 a = base + 16384u + (u32)row * 128u
                            + ((u32)((ks * 2 + cA) ^ (row & 7)) << 4);
                LDSM4(a2[am][0], a2[am][1], a2[am][2], a2[am][3], a);
            }
            #pragma unroll
            for (int am = 0; am < 4; ++am)
                #pragma unroll
                for (int bn = 0; bn < 4; ++bn)
                    mma16816(acc[am][bn], a2[am], bb[bn]);

            // --- reload B with lo, combo 3 (Ah x Bl) ---
            #pragma unroll
            for (int bn = 0; bn < 4; ++bn)
                LDSM2(bb[bn][0], bb[bn][1], baddr[bn] + 16384u);
            #pragma unroll
            for (int am = 0; am < 4; ++am)
                #pragma unroll
                for (int bn = 0; bn < 4; ++bn)
                    mma16816(acc[am][bn], ah[am], bb[bn]);
        }
        if (++sc >= NSTAGE) sc -= NSTAGE;
    }

    // ======================= epilogue =======================
    const int q = lane >> 2, tq = lane & 3;

    if constexpr (MODE == 1) {
        __syncthreads();   // all warps done reading stage smem before T-buffer overwrite
        // transpose 128x128 tile through smem (u32 = packed hi|lo), stride 132
        u32* T = reinterpret_cast<u32*>(smem_ptr);
        #pragma unroll
        for (int am = 0; am < 4; ++am)
            #pragma unroll
            for (int bn = 0; bn < 4; ++bn)
                #pragma unroll
                for (int e = 0; e < 4; ++e) {
                    const int ml = wm * 64 + am * 16 + q + (e >> 1) * 8;
                    const int nl = wn * 32 + bn * 8 + 2 * tq + (e & 1);
                    const float v = acc[am][bn][e] + bias[n0 + nl];
                    const __nv_bfloat16 h = __float2bfloat16(v);
                    const __nv_bfloat16 l = __float2bfloat16(v - __bfloat162float(h));
                    T[nl * 132 + ml] = ((u32)bf_bits(l) << 16) | (u32)bf_bits(h);
                }
        __syncthreads();
        const int d  = tid >> 1;
        const int mh = (tid & 1) * 64;
        const int b  = m0 >> 11;
        const size_t idx = ((size_t)b * CC + (n0 + d)) * TT + (m0 & 2047) + mh;
        #pragma unroll
        for (int i = 0; i < 64; i += 8) {
            u32 hw[4], lw[4];
            #pragma unroll
            for (int p = 0; p < 4; ++p) {
                const u32 t0 = T[d * 132 + mh + i + 2 * p];
                const u32 t1 = T[d * 132 + mh + i + 2 * p + 1];
                hw[p] = (t0 & 0xffffu) | (t1 << 16);
                lw[p] = (t0 >> 16)     | (t1 & 0xffff0000u);
            }
            *reinterpret_cast<uint4*>(outH + idx + i) = make_uint4(hw[0], hw[1], hw[2], hw[3]);
            *reinterpret_cast<uint4*>(outL + idx + i) = make_uint4(lw[0], lw[1], lw[2], lw[3]);
        }
        return;
    } else {

    if (MODE == 0) { outH += z * sCz; outL += z * sCz; }
    else           { outF += z * sCz; }

    #pragma unroll
    for (int am = 0; am < 4; ++am)
        #pragma unroll
        for (int e2 = 0; e2 < 2; ++e2) {
            const int gm = m0 + wm * 64 + am * 16 + q + e2 * 8;
            #pragma unroll
            for (int bn = 0; bn < 4; ++bn) {
                const int gn = n0 + wn * 32 + bn * 8 + 2 * tq;
                float v0 = acc[am][bn][e2 * 2 + 0];
                float v1 = acc[am][bn][e2 * 2 + 1];
                if (MODE == 0) {
                    if (bias) { v0 += bias[gn]; v1 += bias[gn + 1]; }
                    const __nv_bfloat16 h0 = __float2bfloat16(v0), h1 = __float2bfloat16(v1);
                    const __nv_bfloat16 l0 = __float2bfloat16(v0 - __bfloat162float(h0));
                    const __nv_bfloat16 l1 = __float2bfloat16(v1 - __bfloat162float(h1));
                    *reinterpret_cast<u32*>(outH + (size_t)gm * ldc + gn) = pack_bf2(h0, h1);
                    *reinterpret_cast<u32*>(outL + (size_t)gm * ldc + gn) = pack_bf2(l0, l1);
                } else if (MODE == 2) {
                    float2 val; val.x = v0 * scale; val.y = v1 * scale;
                    *reinterpret_cast<float2*>(outF + (size_t)gm * ldc + gn) = val;
                } else {
                    float2 val; val.x = v0 + bias[gn]; val.y = v1 + bias[gn + 1];
                    *reinterpret_cast<float2*>(outF + (size_t)gm * ldc + gn) = val;
                }
            }
        }
    }
}

// ======================= split fp32 -> bf16 hi/lo =======================
__global__ void __launch_bounds__(256) split_kernel(
    const float* __restrict__ x, __nv_bfloat16* __restrict__ h,
    __nv_bfloat16* __restrict__ l, int n4)
{
    int i = blockIdx.x * 256 + threadIdx.x;
    if (i >= n4) return;
    float4 v = reinterpret_cast<const float4*>(x)[i];
    float vv[4] = { v.x, v.y, v.z, v.w };
    __nv_bfloat16 hh[4], ll[4];
    #pragma unroll
    for (int c = 0; c < 4; ++c) {
        hh[c] = __float2bfloat16(vv[c]);
        ll[c] = __float2bfloat16(vv[c] - __bfloat162float(hh[c]));
    }
    *reinterpret_cast<uint2*>(h + 4*(size_t)i) = make_uint2(pack_bf2(hh[0],hh[1]), pack_bf2(hh[2],hh[3]));
    *reinterpret_cast<uint2*>(l + 4*(size_t)i) = make_uint2(pack_bf2(ll[0],ll[1]), pack_bf2(ll[2],ll[3]));
}

// ======================= softmax + split =======================
__global__ void __launch_bounds__(256) softmax_split_kernel(
    const float* __restrict__ S, __nv_bfloat16* __restrict__ Ph, __nv_bfloat16* __restrict__ Pl)
{
    __shared__ float red[8];
    __shared__ float sM, sInv;
    const size_t row = blockIdx.x;
    const float4* src = reinterpret_cast<const float4*>(S + row * TT);
    const int t = threadIdx.x, w = t >> 5, ln = t & 31;

    float4 a = src[t], b2 = src[t + 256];
    float mx = fmaxf(fmaxf(fmaxf(a.x, a.y), fmaxf(a.z, a.w)),
                     fmaxf(fmaxf(b2.x, b2.y), fmaxf(b2.z, b2.w)));
    #pragma unroll
    for (int o = 16; o; o >>= 1) mx = fmaxf(mx, __shfl_xor_sync(0xffffffffu, mx, o));
    if (ln == 0) red[w] = mx;
    __syncthreads();
    if (t == 0) {
        float m = red[0];
        #pragma unroll
        for (int i = 1; i < 8; ++i) m = fmaxf(m, red[i]);
        sM = m;
    }
    __syncthreads();
    const float M = sM;

    float e[8];
    e[0] = __expf(a.x - M);  e[1] = __expf(a.y - M);
    e[2] = __expf(a.z - M);  e[3] = __expf(a.w - M);
    e[4] = __expf(b2.x - M); e[5] = __expf(b2.y - M);
    e[6] = __expf(b2.z - M); e[7] = __expf(b2.w - M);
    float sm = e[0]+e[1]+e[2]+e[3]+e[4]+e[5]+e[6]+e[7];
    #pragma unroll
    for (int o = 16; o; o >>= 1) sm += __shfl_xor_sync(0xffffffffu, sm, o);
    __syncthreads();
    if (ln == 0) red[w] = sm;
    __syncthreads();
    if (t == 0) {
        float ssum = 0.f;
        #pragma unroll
        for (int i = 0; i < 8; ++i) ssum += red[i];
        sInv = 1.0f / ssum;
    }
    __syncthreads();
    const float inv = sInv;

    #pragma unroll
    for (int half = 0; half < 2; ++half) {
        __nv_bfloat16 hh[4], ll[4];
        #pragma unroll
        for (int c = 0; c < 4; ++c) {
            float p = e[half*4 + c] * inv;
            hh[c] = __float2bfloat16(p);
            ll[c] = __float2bfloat16(p - __bfloat162float(hh[c]));
        }
        size_t off = row * TT + (size_t)(t + half*256) * 4;
        *reinterpret_cast<uint2*>(Ph + off) = make_uint2(pack_bf2(hh[0],hh[1]), pack_bf2(hh[2],hh[3]));
        *reinterpret_cast<uint2*>(Pl + off) = make_uint2(pack_bf2(ll[0],ll[1]), pack_bf2(ll[2],ll[3]));
    }
}

// ======================= host launch =======================
static void* sym_addr(const void* s) {
    void* p = nullptr;
    cudaGetSymbolAddress(&p, s);
    return p;
}

extern "C" void kernel_launch(void* const* d_in, const int* in_sizes, int n_in,
                              void* d_out, int out_size) {
    (void)in_sizes; (void)n_in; (void)out_size;
    const float* x  = (const float*)d_in[0];
    const float* Wq = (const float*)d_in[1];
    const float* bq = (const float*)d_in[2];
    const float* Wk = (const float*)d_in[3];
    const float* bk = (const float*)d_in[4];
    const float* Wv = (const float*)d_in[5];
    const float* bv = (const float*)d_in[6];
    const float* Wo = (const float*)d_in[7];
    const float* bo = (const float*)d_in[8];
    float* out = (float*)d_out;

    __nv_bfloat16* xh  = (__nv_bfloat16*)sym_addr(g_xh);
    __nv_bfloat16* xl  = (__nv_bfloat16*)sym_addr(g_xl);
    __nv_bfloat16* wh  = (__nv_bfloat16*)sym_addr(g_wh);
    __nv_bfloat16* wl  = (__nv_bfloat16*)sym_addr(g_wl);
    __nv_bfloat16* qh  = (__nv_bfloat16*)sym_addr(g_qh);
    __nv_bfloat16* ql  = (__nv_bfloat16*)sym_addr(g_ql);
    __nv_bfloat16* kh  = (__nv_bfloat16*)sym_addr(g_kh);
    __nv_bfloat16* kl  = (__nv_bfloat16*)sym_addr(g_kl);
    __nv_bfloat16* vth = (__nv_bfloat16*)sym_addr(g_vth);
    __nv_bfloat16* vtl = (__nv_bfloat16*)sym_addr(g_vtl);
    float*         sS  = (float*)sym_addr(g_s);
    __nv_bfloat16* ph  = (__nv_bfloat16*)sym_addr(g_ph);
    __nv_bfloat16* pl  = (__nv_bfloat16*)sym_addr(g_pl);
    __nv_bfloat16* ch  = (__nv_bfloat16*)sym_addr(g_ch);
    __nv_bfloat16* cl  = (__nv_bfloat16*)sym_addr(g_cl);

    cudaFuncSetAttribute(gemm_bf16x3<0>, cudaFuncAttributeMaxDynamicSharedMemorySize, SMEM_BYTES);
    cudaFuncSetAttribute(gemm_bf16x3<1>, cudaFuncAttributeMaxDynamicSharedMemorySize, SMEM_BYTES);
    cudaFuncSetAttribute(gemm_bf16x3<2>, cudaFuncAttributeMaxDynamicSharedMemorySize, SMEM_BYTES);
    cudaFuncSetAttribute(gemm_bf16x3<3>, cudaFuncAttributeMaxDynamicSharedMemorySize, SMEM_BYTES);

    // splits
    split_kernel<<<(MROWS*CC/4 + 255)/256, 256>>>(x,  xh, xl, MROWS*CC/4);
    split_kernel<<<(CC*CC/4 + 255)/256, 256>>>(Wq, wh + 0*(size_t)CC*CC, wl + 0*(size_t)CC*CC, CC*CC/4);
    split_kernel<<<(CC*CC/4 + 255)/256, 256>>>(Wk, wh + 1*(size_t)CC*CC, wl + 1*(size_t)CC*CC, CC*CC/4);
    split_kernel<<<(CC*CC/4 + 255)/256, 256>>>(Wv, wh + 2*(size_t)CC*CC, wl + 2*(size_t)CC*CC, CC*CC/4);
    split_kernel<<<(CC*CC/4 + 255)/256, 256>>>(Wo, wh + 3*(size_t)CC*CC, wl + 3*(size_t)CC*CC, CC*CC/4);

    dim3 gProj(MROWS/128, CC/128, 1);     // (64, 8, 1)
    // Q = x Wq^T + bq
    gemm_bf16x3<0><<<gProj, 256, SMEM_BYTES>>>(xh, xl, wh + 0*(size_t)CC*CC, wl + 0*(size_t)CC*CC,
        CC, CC, CC, 0, 0, 0, bq, 1.f, qh, ql, nullptr, CC);
    // K
    gemm_bf16x3<0><<<gProj, 256, SMEM_BYTES>>>(xh, xl, wh + 1*(size_t)CC*CC, wl + 1*(size_t)CC*CC,
        CC, CC, CC, 0, 0, 0, bk, 1.f, kh, kl, nullptr, CC);
    // V -> transposed store vt[b][d][s]
    gemm_bf16x3<1><<<gProj, 256, SMEM_BYTES>>>(xh, xl, wh + 2*(size_t)CC*CC, wl + 2*(size_t)CC*CC,
        CC, CC, CC, 0, 0, 0, bv, 1.f, vth, vtl, nullptr, 0);

    // scores = Q K^T / 32  (per batch)
    dim3 gScore(TT/128, TT/128, BN);      // (16, 16, 4)
    gemm_bf16x3<2><<<gScore, 256, SMEM_BYTES>>>(qh, ql, kh, kl,
        CC, CC, CC, (long long)TT*CC, (long long)TT*CC, (long long)TT*TT,
        nullptr, 0.03125f, nullptr, nullptr, sS, TT);

    // softmax + split
    softmax_split_kernel<<<MROWS, 256>>>(sS, ph, pl);

    // ctx = P V  (A = P [t][s], B = vt [d][s], per batch)
    dim3 gPV(TT/128, CC/128, BN);         // (16, 8, 4)
    gemm_bf16x3<0><<<gPV, 256, SMEM_BYTES>>>(ph, pl, vth, vtl,
        TT, TT, TT, (long long)TT*TT, (long long)CC*TT, (long long)TT*CC,
        nullptr, 1.f, ch, cl, nullptr, CC);

    // out = ctx Wo^T + bo  (fp32 -> d_out)
    gemm_bf16x3<3><<<gProj, 256, SMEM_BYTES>>>(ch, cl, wh + 3*(size_t)CC*CC, wl + 3*(size_t)CC*CC,
        CC, CC, CC, 0, 0, 0, bo, 1.f, nullptr, nullptr, out, CC);
}

// round 7
// speedup vs baseline: 1.1764x; 1.0475x over previous
#include <cuda_runtime.h>
#include <cuda_bf16.h>
#include <cstdint>
#include <cstddef>

typedef unsigned int u32;

#define BN 4
#define TT 2048
#define CC 1024
#define MROWS (BN*TT)   // 8192

// ======================= device scratch (no allocs allowed) =======================
__device__ __align__(256) __nv_bfloat16 g_xh[MROWS*CC];
__device__ __align__(256) __nv_bfloat16 g_xl[MROWS*CC];
__device__ __align__(256) __nv_bfloat16 g_wh[4*CC*CC];
__device__ __align__(256) __nv_bfloat16 g_wl[4*CC*CC];
__device__ __align__(256) __nv_bfloat16 g_qh[MROWS*CC];
__device__ __align__(256) __nv_bfloat16 g_ql[MROWS*CC];
__device__ __align__(256) __nv_bfloat16 g_kh[MROWS*CC];
__device__ __align__(256) __nv_bfloat16 g_kl[MROWS*CC];
__device__ __align__(256) __nv_bfloat16 g_vth[MROWS*CC];  // V^T: [b][d][s]
__device__ __align__(256) __nv_bfloat16 g_vtl[MROWS*CC];
__device__ __align__(256) float         g_s [(size_t)BN*TT*TT];
__device__ __align__(256) __nv_bfloat16 g_ph[(size_t)BN*TT*TT];
__device__ __align__(256) __nv_bfloat16 g_pl[(size_t)BN*TT*TT];
__device__ __align__(256) __nv_bfloat16 g_ch[MROWS*CC];
__device__ __align__(256) __nv_bfloat16 g_cl[MROWS*CC];

// ======================= PTX helpers (sm_100 baseline, NO 'a' features) =======================
__device__ __forceinline__ u32 smem_u32(const void* p) {
    u32 a;
    asm("{ .reg .u64 t; cvta.to.shared.u64 t, %1; cvt.u32.u64 %0, t; }" : "=r"(a) : "l"(p));
    return a;
}
__device__ __forceinline__ void cpa16(u32 dst, const void* src) {
    asm volatile("cp.async.cg.shared.global [%0], [%1], 16;" :: "r"(dst), "l"(src) : "memory");
}
#define CP_COMMIT() asm volatile("cp.async.commit_group;" ::: "memory")
#define CP_WAIT(n)  asm volatile("cp.async.wait_group %0;" :: "n"(n) : "memory")

#define LDSM4(d0,d1,d2,d3,a) \
    asm volatile("ldmatrix.sync.aligned.m8n8.x4.shared.b16 {%0,%1,%2,%3}, [%4];" \
                 : "=r"(d0),"=r"(d1),"=r"(d2),"=r"(d3) : "r"(a))
#define LDSM2(d0,d1,a) \
    asm volatile("ldmatrix.sync.aligned.m8n8.x2.shared.b16 {%0,%1}, [%2];" \
                 : "=r"(d0),"=r"(d1) : "r"(a))

__device__ __forceinline__ void mma16816(float* c, const u32* a, const u32* b) {
    asm volatile(
        "mma.sync.aligned.m16n8k16.row.col.f32.bf16.bf16.f32 "
        "{%0,%1,%2,%3}, {%4,%5,%6,%7}, {%8,%9}, {%0,%1,%2,%3};"
        : "+f"(c[0]), "+f"(c[1]), "+f"(c[2]), "+f"(c[3])
        : "r"(a[0]), "r"(a[1]), "r"(a[2]), "r"(a[3]), "r"(b[0]), "r"(b[1]));
}

__device__ __forceinline__ u32 pack_bf2(__nv_bfloat16 a, __nv_bfloat16 b) {
    __nv_bfloat162 t = __halves2bfloat162(a, b);
    return *reinterpret_cast<u32*>(&t);
}
__device__ __forceinline__ unsigned short bf_bits(__nv_bfloat16 h) {
    return *reinterpret_cast<unsigned short*>(&h);
}

// 64B-row swizzle: row*64 + ((c16 ^ ((row>>1)&3)) << 4); bijective over the 8
// 16B slots per 128B phase for any 8 consecutive rows -> conflict-free LDSM.
__device__ __forceinline__ u32 swz64(int row, int c16) {
    return (u32)row * 64u + (u32)((c16 ^ ((row >> 1) & 3)) << 4);
}

// ======================= GEMM kernel =======================
// Tile 128x128, K-chunk 32. Stage: Ah(8K) Al(8K) Bh(8K) Bl(8K) = 32KB; 3 stages.
// 2 CTAs/SM (regs capped at 128, smem 97KB/CTA).
#define ST_BYTES   32768u
#define NSTAGE     3
#define SMEM_BYTES (1024 + NSTAGE*32768)   // 99328

// MODE 0: split bf16 hi/lo row-major (+optional bias, +batch stride on C)
// MODE 1: V-projection: bias then transposed split store into vt[b][d][s]
// MODE 2: fp32 * scale row-major (+batch stride on C)
// MODE 3: fp32 + bias row-major (final output)
template<int MODE>
__global__ void __launch_bounds__(256, 2) gemm_bf16x3(
    const __nv_bfloat16* __restrict__ Ah, const __nv_bfloat16* __restrict__ Al,
    const __nv_bfloat16* __restrict__ Bh, const __nv_bfloat16* __restrict__ Bl,
    int lda, int ldb, int K,
    long long sAz, long long sBz, long long sCz,
    const float* __restrict__ bias, float scale,
    __nv_bfloat16* __restrict__ outH, __nv_bfloat16* __restrict__ outL,
    float* __restrict__ outF, int ldc)
{
    extern __shared__ __align__(1024) char smem_raw[];
    const u32 sb0 = smem_u32(smem_raw);
    const u32 sb  = (sb0 + 1023u) & ~1023u;
    char* smem_ptr = smem_raw + (sb - sb0);

    const int tid  = threadIdx.x;
    const int lane = tid & 31, wid = tid >> 5;
    const int wm = wid & 1, wn = wid >> 1;          // 2 x 4 warp grid
    const int m0 = blockIdx.x * 128, n0 = blockIdx.y * 128;
    const long long z = blockIdx.z;
    Ah += z * sAz; Al += z * sAz; Bh += z * sBz; Bl += z * sBz;

    float acc[4][4][4];
    #pragma unroll
    for (int i = 0; i < 4; ++i)
        #pragma unroll
        for (int j = 0; j < 4; ++j)
            #pragma unroll
            for (int e = 0; e < 4; ++e) acc[i][j][e] = 0.f;

    // ---- cp.async loader: thread t -> row t/2, 2x16B chunks at (t&1)*2 ----
    const int lr  = tid >> 1;
    const int lc0 = (tid & 1) * 2;
    const __nv_bfloat16* gAh = Ah + (size_t)(m0 + lr) * lda + lc0 * 8;
    const __nv_bfloat16* gAl = Al + (size_t)(m0 + lr) * lda + lc0 * 8;
    const __nv_bfloat16* gBh = Bh + (size_t)(n0 + lr) * ldb + lc0 * 8;
    const __nv_bfloat16* gBl = Bl + (size_t)(n0 + lr) * ldb + lc0 * 8;

    auto load_stage = [&](int s, int k0) {
        const u32 b = sb + (u32)s * ST_BYTES;
        #pragma unroll
        for (int j = 0; j < 2; ++j) {
            const u32 dst = b + swz64(lr, lc0 + j);
            cpa16(dst,           gAh + k0 + j * 8);
            cpa16(dst + 8192u,   gAl + k0 + j * 8);
            cpa16(dst + 16384u,  gBh + k0 + j * 8);
            cpa16(dst + 24576u,  gBl + k0 + j * 8);
        }
        CP_COMMIT();
    };

    const int nch = K >> 5;
    load_stage(0, 0);
    load_stage(1, 32);   // all our K >= 128, so nch >= 4 always

    const int rA = lane & 15, cA = lane >> 4;          // ldmatrix x4 lane map (A)
    const int rB = lane & 7,  cB = (lane >> 3) & 1;    // ldmatrix x2 lane map (B)

    int sc = 0;          // stage of chunk c
    for (int c = 0; c < nch; ++c) {
        if (c + 1 < nch) { CP_WAIT(1); } else { CP_WAIT(0); }
        __syncthreads();   // data visibility + all warps done reading stage being overwritten

        // prefetch chunk c+2 into the stage that chunk c-1 just finished with
        if (c + 2 < nch) {
            int sl = sc + 2; if (sl >= NSTAGE) sl -= NSTAGE;
            load_stage(sl, (c + 2) * 32);
        }

        const u32 base = sb + (u32)sc * ST_BYTES;
        #pragma unroll
        for (int ks = 0; ks < 2; ++ks) {
            // --- A-hi + B-hi, combo 1 ---
            u32 ah[4][4];
            #pragma unroll
            for (int am = 0; am < 4; ++am) {
                const int row = wm * 64 + am * 16 + rA;
                LDSM4(ah[am][0], ah[am][1], ah[am][2], ah[am][3],
                      base + swz64(row, ks * 2 + cA));
            }
            u32 bb[4][2];
            #pragma unroll
            for (int bn = 0; bn < 4; ++bn) {
                const int row = wn * 32 + bn * 8 + rB;
                LDSM2(bb[bn][0], bb[bn][1],
                      base + 16384u + swz64(row, ks * 2 + cB));
            }
            #pragma unroll
            for (int am = 0; am < 4; ++am)
                #pragma unroll
                for (int bn = 0; bn < 4; ++bn)
                    mma16816(acc[am][bn], ah[am], bb[bn]);

            // --- A-lo, combo 2 (Al x Bh, reuse bb) ---
            u32 a2[4][4];
            #pragma unroll
            for (int am = 0; am < 4; ++am) {
                const int row = wm * 64 + am * 16 + rA;
                LDSM4(a2[am][0], a2[am][1], a2[am][2], a2[am][3],
                      base + 8192u + swz64(row, ks * 2 + cA));
            }
            #pragma unroll
            for (int am = 0; am < 4; ++am)
                #pragma unroll
                for (int bn = 0; bn < 4; ++bn)
                    mma16816(acc[am][bn], a2[am], bb[bn]);

            // --- reload B with lo, combo 3 (Ah x Bl) ---
            #pragma unroll
            for (int bn = 0; bn < 4; ++bn) {
                const int row = wn * 32 + bn * 8 + rB;
                LDSM2(bb[bn][0], bb[bn][1],
                      base + 24576u + swz64(row, ks * 2 + cB));
            }
            #pragma unroll
            for (int am = 0; am < 4; ++am)
                #pragma unroll
                for (int bn = 0; bn < 4; ++bn)
                    mma16816(acc[am][bn], ah[am], bb[bn]);
        }
        if (++sc >= NSTAGE) sc -= NSTAGE;
    }

    // ======================= epilogue =======================
    const int q = lane >> 2, tq = lane & 3;

    if constexpr (MODE == 1) {
        __syncthreads();   // all warps done with stage smem before T-buffer overwrite
        // transpose 128x128 tile through smem (u32 = packed hi|lo), stride 132
        u32* T = reinterpret_cast<u32*>(smem_ptr);
        #pragma unroll
        for (int am = 0; am < 4; ++am)
            #pragma unroll
            for (int bn = 0; bn < 4; ++bn)
                #pragma unroll
                for (int e = 0; e < 4; ++e) {
                    const int ml = wm * 64 + am * 16 + q + (e >> 1) * 8;
                    const int nl = wn * 32 + bn * 8 + 2 * tq + (e & 1);
                    const float v = acc[am][bn][e] + bias[n0 + nl];
                    const __nv_bfloat16 h = __float2bfloat16(v);
                    const __nv_bfloat16 l = __float2bfloat16(v - __bfloat162float(h));
                    T[nl * 132 + ml] = ((u32)bf_bits(l) << 16) | (u32)bf_bits(h);
                }
        __syncthreads();
        const int d  = tid >> 1;
        const int mh = (tid & 1) * 64;
        const int b  = m0 >> 11;
        const size_t idx = ((size_t)b * CC + (n0 + d)) * TT + (m0 & 2047) + mh;
        #pragma unroll
        for (int i = 0; i < 64; i += 8) {
            u32 hw[4], lw[4];
            #pragma unroll
            for (int p = 0; p < 4; ++p) {
                const u32 t0 = T[d * 132 + mh + i + 2 * p];
                const u32 t1 = T[d * 132 + mh + i + 2 * p + 1];
                hw[p] = (t0 & 0xffffu) | (t1 << 16);
                lw[p] = (t0 >> 16)     | (t1 & 0xffff0000u);
            }
            *reinterpret_cast<uint4*>(outH + idx + i) = make_uint4(hw[0], hw[1], hw[2], hw[3]);
            *reinterpret_cast<uint4*>(outL + idx + i) = make_uint4(lw[0], lw[1], lw[2], lw[3]);
        }
        return;
    } else {

    if (MODE == 0) { outH += z * sCz; outL += z * sCz; }
    else           { outF += z * sCz; }

    #pragma unroll
    for (int am = 0; am < 4; ++am)
        #pragma unroll
        for (int e2 = 0; e2 < 2; ++e2) {
            const int gm = m0 + wm * 64 + am * 16 + q + e2 * 8;
            #pragma unroll
            for (int bn = 0; bn < 4; ++bn) {
                const int gn = n0 + wn * 32 + bn * 8 + 2 * tq;
                float v0 = acc[am][bn][e2 * 2 + 0];
                float v1 = acc[am][bn][e2 * 2 + 1];
                if (MODE == 0) {
                    if (bias) { v0 += bias[gn]; v1 += bias[gn + 1]; }
                    const __nv_bfloat16 h0 = __float2bfloat16(v0), h1 = __float2bfloat16(v1);
                    const __nv_bfloat16 l0 = __float2bfloat16(v0 - __bfloat162float(h0));
                    const __nv_bfloat16 l1 = __float2bfloat16(v1 - __bfloat162float(h1));
                    *reinterpret_cast<u32*>(outH + (size_t)gm * ldc + gn) = pack_bf2(h0, h1);
                    *reinterpret_cast<u32*>(outL + (size_t)gm * ldc + gn) = pack_bf2(l0, l1);
                } else if (MODE == 2) {
                    float2 val; val.x = v0 * scale; val.y = v1 * scale;
                    *reinterpret_cast<float2*>(outF + (size_t)gm * ldc + gn) = val;
                } else {
                    float2 val; val.x = v0 + bias[gn]; val.y = v1 + bias[gn + 1];
                    *reinterpret_cast<float2*>(outF + (size_t)gm * ldc + gn) = val;
                }
            }
        }
    }
}

// ======================= split fp32 -> bf16 hi/lo =======================
__global__ void __launch_bounds__(256) split_kernel(
    const float* __restrict__ x, __nv_bfloat16* __restrict__ h,
    __nv_bfloat16* __restrict__ l, int n4)
{
    int i = blockIdx.x * 256 + threadIdx.x;
    if (i >= n4) return;
    float4 v = reinterpret_cast<const float4*>(x)[i];
    float vv[4] = { v.x, v.y, v.z, v.w };
    __nv_bfloat16 hh[4], ll[4];
    #pragma unroll
    for (int c = 0; c < 4; ++c) {
        hh[c] = __float2bfloat16(vv[c]);
        ll[c] = __float2bfloat16(vv[c] - __bfloat162float(hh[c]));
    }
    *reinterpret_cast<uint2*>(h + 4*(size_t)i) = make_uint2(pack_bf2(hh[0],hh[1]), pack_bf2(hh[2],hh[3]));
    *reinterpret_cast<uint2*>(l + 4*(size_t)i) = make_uint2(pack_bf2(ll[0],ll[1]), pack_bf2(ll[2],ll[3]));
}

// batched weight split: 4 matrices of CC*CC, selected by blockIdx.y
__global__ void __launch_bounds__(256) split_w4_kernel(
    const float* __restrict__ w0, const float* __restrict__ w1,
    const float* __restrict__ w2, const float* __restrict__ w3,
    __nv_bfloat16* __restrict__ h, __nv_bfloat16* __restrict__ l)
{
    const int mat = blockIdx.y;
    const float* src = (mat == 0) ? w0 : (mat == 1) ? w1 : (mat == 2) ? w2 : w3;
    const size_t off = (size_t)mat * CC * CC;
    int i = blockIdx.x * 256 + threadIdx.x;           // i indexes float4
    float4 v = reinterpret_cast<const float4*>(src)[i];
    float vv[4] = { v.x, v.y, v.z, v.w };
    __nv_bfloat16 hh[4], ll[4];
    #pragma unroll
    for (int c = 0; c < 4; ++c) {
        hh[c] = __float2bfloat16(vv[c]);
        ll[c] = __float2bfloat16(vv[c] - __bfloat162float(hh[c]));
    }
    *reinterpret_cast<uint2*>(h + off + 4*(size_t)i) = make_uint2(pack_bf2(hh[0],hh[1]), pack_bf2(hh[2],hh[3]));
    *reinterpret_cast<uint2*>(l + off + 4*(size_t)i) = make_uint2(pack_bf2(ll[0],ll[1]), pack_bf2(ll[2],ll[3]));
}

// ======================= softmax + split =======================
__global__ void __launch_bounds__(256) softmax_split_kernel(
    const float* __restrict__ S, __nv_bfloat16* __restrict__ Ph, __nv_bfloat16* __restrict__ Pl)
{
    __shared__ float red[8];
    __shared__ float sM, sInv;
    const size_t row = blockIdx.x;
    const float4* src = reinterpret_cast<const float4*>(S + row * TT);
    const int t = threadIdx.x, w = t >> 5, ln = t & 31;

    float4 a = src[t], b2 = src[t + 256];
    float mx = fmaxf(fmaxf(fmaxf(a.x, a.y), fmaxf(a.z, a.w)),
                     fmaxf(fmaxf(b2.x, b2.y), fmaxf(b2.z, b2.w)));
    #pragma unroll
    for (int o = 16; o; o >>= 1) mx = fmaxf(mx, __shfl_xor_sync(0xffffffffu, mx, o));
    if (ln == 0) red[w] = mx;
    __syncthreads();
    if (t == 0) {
        float m = red[0];
        #pragma unroll
        for (int i = 1; i < 8; ++i) m = fmaxf(m, red[i]);
        sM = m;
    }
    __syncthreads();
    const float M = sM;

    float e[8];
    e[0] = __expf(a.x - M);  e[1] = __expf(a.y - M);
    e[2] = __expf(a.z - M);  e[3] = __expf(a.w - M);
    e[4] = __expf(b2.x - M); e[5] = __expf(b2.y - M);
    e[6] = __expf(b2.z - M); e[7] = __expf(b2.w - M);
    float sm = e[0]+e[1]+e[2]+e[3]+e[4]+e[5]+e[6]+e[7];
    #pragma unroll
    for (int o = 16; o; o >>= 1) sm += __shfl_xor_sync(0xffffffffu, sm, o);
    __syncthreads();
    if (ln == 0) red[w] = sm;
    __syncthreads();
    if (t == 0) {
        float ssum = 0.f;
        #pragma unroll
        for (int i = 0; i < 8; ++i) ssum += red[i];
        sInv = 1.0f / ssum;
    }
    __syncthreads();
    const float inv = sInv;

    #pragma unroll
    for (int half = 0; half < 2; ++half) {
        __nv_bfloat16 hh[4], ll[4];
        #pragma unroll
        for (int c = 0; c < 4; ++c) {
            float p = e[half*4 + c] * inv;
            hh[c] = __float2bfloat16(p);
            ll[c] = __float2bfloat16(p - __bfloat162float(hh[c]));
        }
        size_t off = row * TT + (size_t)(t + half*256) * 4;
        *reinterpret_cast<uint2*>(Ph + off) = make_uint2(pack_bf2(hh[0],hh[1]), pack_bf2(hh[2],hh[3]));
        *reinterpret_cast<uint2*>(Pl + off) = make_uint2(pack_bf2(ll[0],ll[1]), pack_bf2(ll[2],ll[3]));
    }
}

// ======================= host launch =======================
static void* sym_addr(const void* s) {
    void* p = nullptr;
    cudaGetSymbolAddress(&p, s);
    return p;
}

extern "C" void kernel_launch(void* const* d_in, const int* in_sizes, int n_in,
                              void* d_out, int out_size) {
    (void)in_sizes; (void)n_in; (void)out_size;
    const float* x  = (const float*)d_in[0];
    const float* Wq = (const float*)d_in[1];
    const float* bq = (const float*)d_in[2];
    const float* Wk = (const float*)d_in[3];
    const float* bk = (const float*)d_in[4];
    const float* Wv = (const float*)d_in[5];
    const float* bv = (const float*)d_in[6];
    const float* Wo = (const float*)d_in[7];
    const float* bo = (const float*)d_in[8];
    float* out = (float*)d_out;

    __nv_bfloat16* xh  = (__nv_bfloat16*)sym_addr(g_xh);
    __nv_bfloat16* xl  = (__nv_bfloat16*)sym_addr(g_xl);
    __nv_bfloat16* wh  = (__nv_bfloat16*)sym_addr(g_wh);
    __nv_bfloat16* wl  = (__nv_bfloat16*)sym_addr(g_wl);
    __nv_bfloat16* qh  = (__nv_bfloat16*)sym_addr(g_qh);
    __nv_bfloat16* ql  = (__nv_bfloat16*)sym_addr(g_ql);
    __nv_bfloat16* kh  = (__nv_bfloat16*)sym_addr(g_kh);
    __nv_bfloat16* kl  = (__nv_bfloat16*)sym_addr(g_kl);
    __nv_bfloat16* vth = (__nv_bfloat16*)sym_addr(g_vth);
    __nv_bfloat16* vtl = (__nv_bfloat16*)sym_addr(g_vtl);
    float*         sS  = (float*)sym_addr(g_s);
    __nv_bfloat16* ph  = (__nv_bfloat16*)sym_addr(g_ph);
    __nv_bfloat16* pl  = (__nv_bfloat16*)sym_addr(g_pl);
    __nv_bfloat16* ch  = (__nv_bfloat16*)sym_addr(g_ch);
    __nv_bfloat16* cl  = (__nv_bfloat16*)sym_addr(g_cl);

    cudaFuncSetAttribute(gemm_bf16x3<0>, cudaFuncAttributeMaxDynamicSharedMemorySize, SMEM_BYTES);
    cudaFuncSetAttribute(gemm_bf16x3<1>, cudaFuncAttributeMaxDynamicSharedMemorySize, SMEM_BYTES);
    cudaFuncSetAttribute(gemm_bf16x3<2>, cudaFuncAttributeMaxDynamicSharedMemorySize, SMEM_BYTES);
    cudaFuncSetAttribute(gemm_bf16x3<3>, cudaFuncAttributeMaxDynamicSharedMemorySize, SMEM_BYTES);

    // launch 0: split x; launch 1: split 4 weights (batched)
    split_kernel<<<(MROWS*CC/4 + 255)/256, 256>>>(x, xh, xl, MROWS*CC/4);
    dim3 gW(CC*CC/4/256, 4);
    split_w4_kernel<<<gW, 256>>>(Wq, Wk, Wv, Wo, wh, wl);

    dim3 gProj(MROWS/128, CC/128, 1);     // (64, 8, 1)
    // launch 2: Q = x Wq^T + bq
    gemm_bf16x3<0><<<gProj, 256, SMEM_BYTES>>>(xh, xl, wh + 0*(size_t)CC*CC, wl + 0*(size_t)CC*CC,
        CC, CC, CC, 0, 0, 0, bq, 1.f, qh, ql, nullptr, CC);
    // launch 3: K
    gemm_bf16x3<0><<<gProj, 256, SMEM_BYTES>>>(xh, xl, wh + 1*(size_t)CC*CC, wl + 1*(size_t)CC*CC,
        CC, CC, CC, 0, 0, 0, bk, 1.f, kh, kl, nullptr, CC);
    // launch 4: V -> transposed store vt[b][d][s]
    gemm_bf16x3<1><<<gProj, 256, SMEM_BYTES>>>(xh, xl, wh + 2*(size_t)CC*CC, wl + 2*(size_t)CC*CC,
        CC, CC, CC, 0, 0, 0, bv, 1.f, vth, vtl, nullptr, 0);

    // launch 5 (ncu -s 5 -c 1 profiles this): scores = Q K^T / 32  (per batch)
    dim3 gScore(TT/128, TT/128, BN);      // (16, 16, 4)
    gemm_bf16x3<2><<<gScore, 256, SMEM_BYTES>>>(qh, ql, kh, kl,
        CC, CC, CC, (long long)TT*CC, (long long)TT*CC, (long long)TT*TT,
        nullptr, 0.03125f, nullptr, nullptr, sS, TT);

    // softmax + split
    softmax_split_kernel<<<MROWS, 256>>>(sS, ph, pl);

    // ctx = P V  (A = P [t][s], B = vt [d][s], per batch)
    dim3 gPV(TT/128, CC/128, BN);         // (16, 8, 4)
    gemm_bf16x3<0><<<gPV, 256, SMEM_BYTES>>>(ph, pl, vth, vtl,
        TT, TT, TT, (long long)TT*TT, (long long)CC*TT, (long long)TT*CC,
        nullptr, 1.f, ch, cl, nullptr, CC);

    // out = ctx Wo^T + bo  (fp32 -> d_out)
    gemm_bf16x3<3><<<gProj, 256, SMEM_BYTES>>>(ch, cl, wh + 3*(size_t)CC*CC, wl + 3*(size_t)CC*CC,
        CC, CC, CC, 0, 0, 0, bo, 1.f, nullptr, nullptr, out, CC);
}

// round 8
// speedup vs baseline: 1.2307x; 1.0462x over previous
#include <cuda_runtime.h>
#include <cuda_bf16.h>
#include <cstdint>
#include <cstddef>

typedef unsigned int u32;

#define BN 4
#define TT 2048
#define CC 1024
#define MROWS (BN*TT)   // 8192

// ======================= device scratch (no allocs allowed) =======================
__device__ __align__(256) __nv_bfloat16 g_xh[MROWS*CC];
__device__ __align__(256) __nv_bfloat16 g_xl[MROWS*CC];
__device__ __align__(256) __nv_bfloat16 g_wh[4*CC*CC];
__device__ __align__(256) __nv_bfloat16 g_wl[4*CC*CC];
__device__ __align__(256) __nv_bfloat16 g_qh[MROWS*CC];
__device__ __align__(256) __nv_bfloat16 g_ql[MROWS*CC];
__device__ __align__(256) __nv_bfloat16 g_kh[MROWS*CC];
__device__ __align__(256) __nv_bfloat16 g_kl[MROWS*CC];
__device__ __align__(256) __nv_bfloat16 g_vth[MROWS*CC];  // V^T: [b][d][s]
__device__ __align__(256) __nv_bfloat16 g_vtl[MROWS*CC];
__device__ __align__(256) float         g_s [(size_t)BN*TT*TT];
__device__ __align__(256) __nv_bfloat16 g_ph[(size_t)BN*TT*TT];
__device__ __align__(256) __nv_bfloat16 g_pl[(size_t)BN*TT*TT];
__device__ __align__(256) __nv_bfloat16 g_ch[MROWS*CC];
__device__ __align__(256) __nv_bfloat16 g_cl[MROWS*CC];

// ======================= PTX helpers (sm_100 baseline, NO 'a' features) =======================
__device__ __forceinline__ u32 smem_u32(const void* p) {
    u32 a;
    asm("{ .reg .u64 t; cvta.to.shared.u64 t, %1; cvt.u32.u64 %0, t; }" : "=r"(a) : "l"(p));
    return a;
}
__device__ __forceinline__ void cpa16(u32 dst, const void* src) {
    asm volatile("cp.async.cg.shared.global [%0], [%1], 16;" :: "r"(dst), "l"(src) : "memory");
}
#define CP_COMMIT() asm volatile("cp.async.commit_group;" ::: "memory")
#define CP_WAIT(n)  asm volatile("cp.async.wait_group %0;" :: "n"(n) : "memory")

#define LDSM4(d0,d1,d2,d3,a) \
    asm volatile("ldmatrix.sync.aligned.m8n8.x4.shared.b16 {%0,%1,%2,%3}, [%4];" \
                 : "=r"(d0),"=r"(d1),"=r"(d2),"=r"(d3) : "r"(a))
#define LDSM2(d0,d1,a) \
    asm volatile("ldmatrix.sync.aligned.m8n8.x2.shared.b16 {%0,%1}, [%2];" \
                 : "=r"(d0),"=r"(d1) : "r"(a))

__device__ __forceinline__ void mma16816(float* c, const u32* a, const u32* b) {
    asm volatile(
        "mma.sync.aligned.m16n8k16.row.col.f32.bf16.bf16.f32 "
        "{%0,%1,%2,%3}, {%4,%5,%6,%7}, {%8,%9}, {%0,%1,%2,%3};"
        : "+f"(c[0]), "+f"(c[1]), "+f"(c[2]), "+f"(c[3])
        : "r"(a[0]), "r"(a[1]), "r"(a[2]), "r"(a[3]), "r"(b[0]), "r"(b[1]));
}

__device__ __forceinline__ u32 pack_bf2(__nv_bfloat16 a, __nv_bfloat16 b) {
    __nv_bfloat162 t = __halves2bfloat162(a, b);
    return *reinterpret_cast<u32*>(&t);
}
__device__ __forceinline__ unsigned short bf_bits(__nv_bfloat16 h) {
    return *reinterpret_cast<unsigned short*>(&h);
}

// 64B-row swizzle: row*64 + ((c16 ^ ((row>>1)&3)) << 4); bijective over the 8
// 16B slots per 128B phase; additive in row steps of 8/16 (bits >=3 of row>>1
// don't change the &3 term) -> LDSM addresses are base + constant.
__device__ __forceinline__ u32 swz64(int row, int c16) {
    return (u32)row * 64u + (u32)((c16 ^ ((row >> 1) & 3)) << 4);
}

// ======================= GEMM kernel =======================
// Tile 128x128, K-chunk 32. Stage: Ah(8K) Al(8K) Bh(8K) Bl(8K) = 32KB; 3 stages.
// 2 CTAs/SM (regs capped at 128, smem 97KB/CTA).
#define ST_BYTES   32768u
#define NSTAGE     3
#define SMEM_BYTES (1024 + NSTAGE*32768)   // 99328

// MODE 0: split bf16 hi/lo row-major (+optional bias, +batch stride on C)
// MODE 1: V-projection: bias then transposed split store into vt[b][d][s]
// MODE 2: fp32 * scale row-major (+batch stride on C)
// MODE 3: fp32 + bias row-major (final output)
template<int MODE>
__global__ void __launch_bounds__(256, 2) gemm_bf16x3(
    const __nv_bfloat16* __restrict__ Ah, const __nv_bfloat16* __restrict__ Al,
    const __nv_bfloat16* __restrict__ Bh, const __nv_bfloat16* __restrict__ Bl,
    int lda, int ldb, int K,
    long long sAz, long long sBz, long long sCz,
    const float* __restrict__ bias, float scale,
    __nv_bfloat16* __restrict__ outH, __nv_bfloat16* __restrict__ outL,
    float* __restrict__ outF, int ldc)
{
    extern __shared__ __align__(1024) char smem_raw[];
    const u32 sb0 = smem_u32(smem_raw);
    const u32 sb  = (sb0 + 1023u) & ~1023u;
    char* smem_ptr = smem_raw + (sb - sb0);

    const int tid  = threadIdx.x;
    const int lane = tid & 31, wid = tid >> 5;
    const int wm = wid & 1, wn = wid >> 1;          // 2 x 4 warp grid
    const int m0 = blockIdx.x * 128, n0 = blockIdx.y * 128;
    const long long z = blockIdx.z;
    Ah += z * sAz; Al += z * sAz; Bh += z * sBz; Bl += z * sBz;

    float acc[4][4][4];
    #pragma unroll
    for (int i = 0; i < 4; ++i)
        #pragma unroll
        for (int j = 0; j < 4; ++j)
            #pragma unroll
            for (int e = 0; e < 4; ++e) acc[i][j][e] = 0.f;

    // ---- cp.async loader: thread t -> row t/2, 2x16B chunks at (t&1)*2 ----
    const int lr  = tid >> 1;
    const int lc0 = (tid & 1) * 2;
    const __nv_bfloat16* gAh = Ah + (size_t)(m0 + lr) * lda + lc0 * 8;
    const __nv_bfloat16* gAl = Al + (size_t)(m0 + lr) * lda + lc0 * 8;
    const __nv_bfloat16* gBh = Bh + (size_t)(n0 + lr) * ldb + lc0 * 8;
    const __nv_bfloat16* gBl = Bl + (size_t)(n0 + lr) * ldb + lc0 * 8;

    auto load_stage = [&](int s, int k0) {
        const u32 b = sb + (u32)s * ST_BYTES;
        #pragma unroll
        for (int j = 0; j < 2; ++j) {
            const u32 dst = b + swz64(lr, lc0 + j);
            cpa16(dst,           gAh + k0 + j * 8);
            cpa16(dst + 8192u,   gAl + k0 + j * 8);
            cpa16(dst + 16384u,  gBh + k0 + j * 8);
            cpa16(dst + 24576u,  gBl + k0 + j * 8);
        }
        CP_COMMIT();
    };

    const int nch = K >> 5;
    load_stage(0, 0);
    load_stage(1, 32);   // all our K >= 128, so nch >= 4 always

    const int rA = lane & 15, cA = lane >> 4;          // ldmatrix x4 lane map (A)
    const int rB = lane & 7,  cB = (lane >> 3) & 1;    // ldmatrix x2 lane map (B)

    // loop-invariant swizzled offsets (A: +am*1024 per 16 rows; B: +bn*512 per 8 rows)
    const u32 offA0 = swz64(wm * 64 + rA, cA);
    const u32 offA1 = swz64(wm * 64 + rA, 2 + cA);
    const u32 offB0 = swz64(wn * 32 + rB, cB);
    const u32 offB1 = swz64(wn * 32 + rB, 2 + cB);

    int sc = 0;          // stage of chunk c
    for (int c = 0; c < nch; ++c) {
        if (c + 1 < nch) { CP_WAIT(1); } else { CP_WAIT(0); }
        __syncthreads();   // data visibility + all warps done reading stage being overwritten

        // prefetch chunk c+2 into the stage that chunk c-1 just finished with
        if (c + 2 < nch) {
            int sl = sc + 2; if (sl >= NSTAGE) sl -= NSTAGE;
            load_stage(sl, (c + 2) * 32);
        }

        const u32 base = sb + (u32)sc * ST_BYTES;
        #pragma unroll
        for (int ks = 0; ks < 2; ++ks) {
            const u32 aoff = base + (ks ? offA1 : offA0);
            const u32 boff = base + 16384u + (ks ? offB1 : offB0);

            // resident B: hi and lo for all 4 bn (16 regs)
            u32 bh[4][2], bl[4][2];
            #pragma unroll
            for (int bn = 0; bn < 4; ++bn)
                LDSM2(bh[bn][0], bh[bn][1], boff + (u32)bn * 512u);
            #pragma unroll
            for (int bn = 0; bn < 4; ++bn)
                LDSM2(bl[bn][0], bl[bn][1], boff + 8192u + (u32)bn * 512u);

            // stream A: per am load hi+lo (8 regs), fire 12 MMAs
            #pragma unroll
            for (int am = 0; am < 4; ++am) {
                u32 ah[4], al[4];
                LDSM4(ah[0], ah[1], ah[2], ah[3], aoff + (u32)am * 1024u);
                LDSM4(al[0], al[1], al[2], al[3], aoff + 8192u + (u32)am * 1024u);
                #pragma unroll
                for (int bn = 0; bn < 4; ++bn)
                    mma16816(acc[am][bn], ah, bh[bn]);
                #pragma unroll
                for (int bn = 0; bn < 4; ++bn)
                    mma16816(acc[am][bn], al, bh[bn]);
                #pragma unroll
                for (int bn = 0; bn < 4; ++bn)
                    mma16816(acc[am][bn], ah, bl[bn]);
            }
        }
        if (++sc >= NSTAGE) sc -= NSTAGE;
    }

    // ======================= epilogue =======================
    const int q = lane >> 2, tq = lane & 3;

    if constexpr (MODE == 1) {
        __syncthreads();   // all warps done with stage smem before T-buffer overwrite
        // transpose 128x128 tile through smem (u32 = packed hi|lo), stride 132
        u32* T = reinterpret_cast<u32*>(smem_ptr);
        #pragma unroll
        for (int am = 0; am < 4; ++am)
            #pragma unroll
            for (int bn = 0; bn < 4; ++bn)
                #pragma unroll
                for (int e = 0; e < 4; ++e) {
                    const int ml = wm * 64 + am * 16 + q + (e >> 1) * 8;
                    const int nl = wn * 32 + bn * 8 + 2 * tq + (e & 1);
                    const float v = acc[am][bn][e] + bias[n0 + nl];
                    const __nv_bfloat16 h = __float2bfloat16(v);
                    const __nv_bfloat16 l = __float2bfloat16(v - __bfloat162float(h));
                    T[nl * 132 + ml] = ((u32)bf_bits(l) << 16) | (u32)bf_bits(h);
                }
        __syncthreads();
        const int d  = tid >> 1;
        const int mh = (tid & 1) * 64;
        const int b  = m0 >> 11;
        const size_t idx = ((size_t)b * CC + (n0 + d)) * TT + (m0 & 2047) + mh;
        #pragma unroll
        for (int i = 0; i < 64; i += 8) {
            u32 hw[4], lw[4];
            #pragma unroll
            for (int p = 0; p < 4; ++p) {
                const u32 t0 = T[d * 132 + mh + i + 2 * p];
                const u32 t1 = T[d * 132 + mh + i + 2 * p + 1];
                hw[p] = (t0 & 0xffffu) | (t1 << 16);
                lw[p] = (t0 >> 16)     | (t1 & 0xffff0000u);
            }
            *reinterpret_cast<uint4*>(outH + idx + i) = make_uint4(hw[0], hw[1], hw[2], hw[3]);
            *reinterpret_cast<uint4*>(outL + idx + i) = make_uint4(lw[0], lw[1], lw[2], lw[3]);
        }
        return;
    } else {

    if (MODE == 0) { outH += z * sCz; outL += z * sCz; }
    else           { outF += z * sCz; }

    #pragma unroll
    for (int am = 0; am < 4; ++am)
        #pragma unroll
        for (int e2 = 0; e2 < 2; ++e2) {
            const int gm = m0 + wm * 64 + am * 16 + q + e2 * 8;
            #pragma unroll
            for (int bn = 0; bn < 4; ++bn) {
                const int gn = n0 + wn * 32 + bn * 8 + 2 * tq;
                float v0 = acc[am][bn][e2 * 2 + 0];
                float v1 = acc[am][bn][e2 * 2 + 1];
                if (MODE == 0) {
                    if (bias) { v0 += bias[gn]; v1 += bias[gn + 1]; }
                    const __nv_bfloat16 h0 = __float2bfloat16(v0), h1 = __float2bfloat16(v1);
                    const __nv_bfloat16 l0 = __float2bfloat16(v0 - __bfloat162float(h0));
                    const __nv_bfloat16 l1 = __float2bfloat16(v1 - __bfloat162float(h1));
                    *reinterpret_cast<u32*>(outH + (size_t)gm * ldc + gn) = pack_bf2(h0, h1);
                    *reinterpret_cast<u32*>(outL + (size_t)gm * ldc + gn) = pack_bf2(l0, l1);
                } else if (MODE == 2) {
                    float2 val; val.x = v0 * scale; val.y = v1 * scale;
                    *reinterpret_cast<float2*>(outF + (size_t)gm * ldc + gn) = val;
                } else {
                    float2 val; val.x = v0 + bias[gn]; val.y = v1 + bias[gn + 1];
                    *reinterpret_cast<float2*>(outF + (size_t)gm * ldc + gn) = val;
                }
            }
        }
    }
}

// ======================= split fp32 -> bf16 hi/lo =======================
__global__ void __launch_bounds__(256) split_kernel(
    const float* __restrict__ x, __nv_bfloat16* __restrict__ h,
    __nv_bfloat16* __restrict__ l, int n4)
{
    int i = blockIdx.x * 256 + threadIdx.x;
    if (i >= n4) return;
    float4 v = reinterpret_cast<const float4*>(x)[i];
    float vv[4] = { v.x, v.y, v.z, v.w };
    __nv_bfloat16 hh[4], ll[4];
    #pragma unroll
    for (int c = 0; c < 4; ++c) {
        hh[c] = __float2bfloat16(vv[c]);
        ll[c] = __float2bfloat16(vv[c] - __bfloat162float(hh[c]));
    }
    *reinterpret_cast<uint2*>(h + 4*(size_t)i) = make_uint2(pack_bf2(hh[0],hh[1]), pack_bf2(hh[2],hh[3]));
    *reinterpret_cast<uint2*>(l + 4*(size_t)i) = make_uint2(pack_bf2(ll[0],ll[1]), pack_bf2(ll[2],ll[3]));
}

// batched weight split: 4 matrices of CC*CC, selected by blockIdx.y
__global__ void __launch_bounds__(256) split_w4_kernel(
    const float* __restrict__ w0, const float* __restrict__ w1,
    const float* __restrict__ w2, const float* __restrict__ w3,
    __nv_bfloat16* __restrict__ h, __nv_bfloat16* __restrict__ l)
{
    const int mat = blockIdx.y;
    const float* src = (mat == 0) ? w0 : (mat == 1) ? w1 : (mat == 2) ? w2 : w3;
    const size_t off = (size_t)mat * CC * CC;
    int i = blockIdx.x * 256 + threadIdx.x;           // i indexes float4
    float4 v = reinterpret_cast<const float4*>(src)[i];
    float vv[4] = { v.x, v.y, v.z, v.w };
    __nv_bfloat16 hh[4], ll[4];
    #pragma unroll
    for (int c = 0; c < 4; ++c) {
        hh[c] = __float2bfloat16(vv[c]);
        ll[c] = __float2bfloat16(vv[c] - __bfloat162float(hh[c]));
    }
    *reinterpret_cast<uint2*>(h + off + 4*(size_t)i) = make_uint2(pack_bf2(hh[0],hh[1]), pack_bf2(hh[2],hh[3]));
    *reinterpret_cast<uint2*>(l + off + 4*(size_t)i) = make_uint2(pack_bf2(ll[0],ll[1]), pack_bf2(ll[2],ll[3]));
}

// ======================= softmax + split =======================
__global__ void __launch_bounds__(256) softmax_split_kernel(
    const float* __restrict__ S, __nv_bfloat16* __restrict__ Ph, __nv_bfloat16* __restrict__ Pl)
{
    __shared__ float red[8];
    __shared__ float sM, sInv;
    const size_t row = blockIdx.x;
    const float4* src = reinterpret_cast<const float4*>(S + row * TT);
    const int t = threadIdx.x, w = t >> 5, ln = t & 31;

    float4 a = src[t], b2 = src[t + 256];
    float mx = fmaxf(fmaxf(fmaxf(a.x, a.y), fmaxf(a.z, a.w)),
                     fmaxf(fmaxf(b2.x, b2.y), fmaxf(b2.z, b2.w)));
    #pragma unroll
    for (int o = 16; o; o >>= 1) mx = fmaxf(mx, __shfl_xor_sync(0xffffffffu, mx, o));
    if (ln == 0) red[w] = mx;
    __syncthreads();
    if (t == 0) {
        float m = red[0];
        #pragma unroll
        for (int i = 1; i < 8; ++i) m = fmaxf(m, red[i]);
        sM = m;
    }
    __syncthreads();
    const float M = sM;

    float e[8];
    e[0] = __expf(a.x - M);  e[1] = __expf(a.y - M);
    e[2] = __expf(a.z - M);  e[3] = __expf(a.w - M);
    e[4] = __expf(b2.x - M); e[5] = __expf(b2.y - M);
    e[6] = __expf(b2.z - M); e[7] = __expf(b2.w - M);
    float sm = e[0]+e[1]+e[2]+e[3]+e[4]+e[5]+e[6]+e[7];
    #pragma unroll
    for (int o = 16; o; o >>= 1) sm += __shfl_xor_sync(0xffffffffu, sm, o);
    __syncthreads();
    if (ln == 0) red[w] = sm;
    __syncthreads();
    if (t == 0) {
        float ssum = 0.f;
        #pragma unroll
        for (int i = 0; i < 8; ++i) ssum += red[i];
        sInv = 1.0f / ssum;
    }
    __syncthreads();
    const float inv = sInv;

    #pragma unroll
    for (int half = 0; half < 2; ++half) {
        __nv_bfloat16 hh[4], ll[4];
        #pragma unroll
        for (int c = 0; c < 4; ++c) {
            float p = e[half*4 + c] * inv;
            hh[c] = __float2bfloat16(p);
            ll[c] = __float2bfloat16(p - __bfloat162float(hh[c]));
        }
        size_t off = row * TT + (size_t)(t + half*256) * 4;
        *reinterpret_cast<uint2*>(Ph + off) = make_uint2(pack_bf2(hh[0],hh[1]), pack_bf2(hh[2],hh[3]));
        *reinterpret_cast<uint2*>(Pl + off) = make_uint2(pack_bf2(ll[0],ll[1]), pack_bf2(ll[2],ll[3]));
    }
}

// ======================= host launch =======================
static void* sym_addr(const void* s) {
    void* p = nullptr;
    cudaGetSymbolAddress(&p, s);
    return p;
}

extern "C" void kernel_launch(void* const* d_in, const int* in_sizes, int n_in,
                              void* d_out, int out_size) {
    (void)in_sizes; (void)n_in; (void)out_size;
    const float* x  = (const float*)d_in[0];
    const float* Wq = (const float*)d_in[1];
    const float* bq = (const float*)d_in[2];
    const float* Wk = (const float*)d_in[3];
    const float* bk = (const float*)d_in[4];
    const float* Wv = (const float*)d_in[5];
    const float* bv = (const float*)d_in[6];
    const float* Wo = (const float*)d_in[7];
    const float* bo = (const float*)d_in[8];
    float* out = (float*)d_out;

    __nv_bfloat16* xh  = (__nv_bfloat16*)sym_addr(g_xh);
    __nv_bfloat16* xl  = (__nv_bfloat16*)sym_addr(g_xl);
    __nv_bfloat16* wh  = (__nv_bfloat16*)sym_addr(g_wh);
    __nv_bfloat16* wl  = (__nv_bfloat16*)sym_addr(g_wl);
    __nv_bfloat16* qh  = (__nv_bfloat16*)sym_addr(g_qh);
    __nv_bfloat16* ql  = (__nv_bfloat16*)sym_addr(g_ql);
    __nv_bfloat16* kh  = (__nv_bfloat16*)sym_addr(g_kh);
    __nv_bfloat16* kl  = (__nv_bfloat16*)sym_addr(g_kl);
    __nv_bfloat16* vth = (__nv_bfloat16*)sym_addr(g_vth);
    __nv_bfloat16* vtl = (__nv_bfloat16*)sym_addr(g_vtl);
    float*         sS  = (float*)sym_addr(g_s);
    __nv_bfloat16* ph  = (__nv_bfloat16*)sym_addr(g_ph);
    __nv_bfloat16* pl  = (__nv_bfloat16*)sym_addr(g_pl);
    __nv_bfloat16* ch  = (__nv_bfloat16*)sym_addr(g_ch);
    __nv_bfloat16* cl  = (__nv_bfloat16*)sym_addr(g_cl);

    cudaFuncSetAttribute(gemm_bf16x3<0>, cudaFuncAttributeMaxDynamicSharedMemorySize, SMEM_BYTES);
    cudaFuncSetAttribute(gemm_bf16x3<1>, cudaFuncAttributeMaxDynamicSharedMemorySize, SMEM_BYTES);
    cudaFuncSetAttribute(gemm_bf16x3<2>, cudaFuncAttributeMaxDynamicSharedMemorySize, SMEM_BYTES);
    cudaFuncSetAttribute(gemm_bf16x3<3>, cudaFuncAttributeMaxDynamicSharedMemorySize, SMEM_BYTES);

    // launch 0: split x; launch 1: split 4 weights (batched)
    split_kernel<<<(MROWS*CC/4 + 255)/256, 256>>>(x, xh, xl, MROWS*CC/4);
    dim3 gW(CC*CC/4/256, 4);
    split_w4_kernel<<<gW, 256>>>(Wq, Wk, Wv, Wo, wh, wl);

    dim3 gProj(MROWS/128, CC/128, 1);     // (64, 8, 1)
    // launch 2: Q = x Wq^T + bq
    gemm_bf16x3<0><<<gProj, 256, SMEM_BYTES>>>(xh, xl, wh + 0*(size_t)CC*CC, wl + 0*(size_t)CC*CC,
        CC, CC, CC, 0, 0, 0, bq, 1.f, qh, ql, nullptr, CC);
    // launch 3: K
    gemm_bf16x3<0><<<gProj, 256, SMEM_BYTES>>>(xh, xl, wh + 1*(size_t)CC*CC, wl + 1*(size_t)CC*CC,
        CC, CC, CC, 0, 0, 0, bk, 1.f, kh, kl, nullptr, CC);
    // launch 4: V -> transposed store vt[b][d][s]
    gemm_bf16x3<1><<<gProj, 256, SMEM_BYTES>>>(xh, xl, wh + 2*(size_t)CC*CC, wl + 2*(size_t)CC*CC,
        CC, CC, CC, 0, 0, 0, bv, 1.f, vth, vtl, nullptr, 0);

    // launch 5: scores = Q K^T / 32  (per batch)
    dim3 gScore(TT/128, TT/128, BN);      // (16, 16, 4)
    gemm_bf16x3<2><<<gScore, 256, SMEM_BYTES>>>(qh, ql, kh, kl,
        CC, CC, CC, (long long)TT*CC, (long long)TT*CC, (long long)TT*TT,
        nullptr, 0.03125f, nullptr, nullptr, sS, TT);

    // softmax + split
    softmax_split_kernel<<<MROWS, 256>>>(sS, ph, pl);

    // ctx = P V  (A = P [t][s], B = vt [d][s], per batch)
    dim3 gPV(TT/128, CC/128, BN);         // (16, 8, 4)
    gemm_bf16x3<0><<<gPV, 256, SMEM_BYTES>>>(ph, pl, vth, vtl,
        TT, TT, TT, (long long)TT*TT, (long long)CC*TT, (long long)TT*CC,
        nullptr, 1.f, ch, cl, nullptr, CC);

    // out = ctx Wo^T + bo  (fp32 -> d_out)
    gemm_bf16x3<3><<<gProj, 256, SMEM_BYTES>>>(ch, cl, wh + 3*(size_t)CC*CC, wl + 3*(size_t)CC*CC,
        CC, CC, CC, 0, 0, 0, bo, 1.f, nullptr, nullptr, out, CC);
}